// round 4
// baseline (speedup 1.0000x reference)
#include <cuda_runtime.h>
#include <cuda_bf16.h>
#include <cstdint>

// ---------------- problem constants ----------------
#define NN      100000
#define EE      250000
#define HH      4
#define CC      32
#define HD      128
#define DIN     128
#define NOUT    349

// ---------------- device scratch ----------------
__device__ float g_H  [3 * NN * HD];   // per-relation h_s
__device__ float g_ACC[3 * NN * HD];   // XP1, XA1, XP2 (one memset)
__device__ float g_P  [6 * NN * HH];   // projection outputs
__device__ float g_Z  [5 * NN * HH];   // softmax denominators (3 L0 + 2 L1)
__device__ float g_EW [3 * EE * HH];   // per-edge exp weights
__device__ float g_V  [10 * DIN * HH]; // projected attention vectors
__device__ float g_LB2[NOUT];          // folded classifier bias

// ---------------- prep: V vectors + folded classifier bias ----------------
struct PrepParams {
    const float* W[10];
    const float* att[10];
    float* V;
    const float* linW;
    const float* linb;
    const float* bc;   // b1_c
    const float* bw;   // b1_w
    float* linb2;
};

__global__ void prep_all_kernel(PrepParams p)
{
    int b = blockIdx.x;
    if (b < 10) {
        int k = threadIdx.x;
        if (k >= DIN) return;
        const float* W   = p.W[b];
        const float* att = p.att[b];
        #pragma unroll
        for (int h = 0; h < HH; h++) {
            float s = 0.f;
            #pragma unroll
            for (int c = 0; c < CC; c++)
                s += W[k * HD + h * CC + c] * att[h * CC + c];
            p.V[b * (DIN * HH) + k * HH + h] = s;
        }
    } else {
        int o = (b - 10) * 256 + threadIdx.x;
        if (o >= NOUT) return;
        float s = p.linb[o];
        #pragma unroll 4
        for (int j = 0; j < HD; j++)
            s += (p.bc[j] + p.bw[j]) * p.linW[(size_t)j * NOUT + o];
        p.linb2[o] = s;
    }
}

// ---------------- layer-0 projections (no bias) ----------------
template <int NV>
__global__ void __launch_bounds__(256) proj_multi_kernel(
    const float* __restrict__ x, const float* __restrict__ V,
    float* __restrict__ o0, float* __restrict__ o1,
    float* __restrict__ o2, float* __restrict__ o3, int n)
{
    int lane   = threadIdx.x & 31;
    int warp   = (blockIdx.x * blockDim.x + threadIdx.x) >> 5;
    int nwarps = (gridDim.x * blockDim.x) >> 5;

    const float4* V4 = reinterpret_cast<const float4*>(V);
    float4 vv[NV][4];
    #pragma unroll
    for (int v = 0; v < NV; v++)
        #pragma unroll
        for (int q = 0; q < 4; q++)
            vv[v][q] = V4[v * 128 + lane * 4 + q];

    float* outs[4] = {o0, o1, o2, o3};
    const float4* x4 = reinterpret_cast<const float4*>(x);

    for (int node = warp; node < n; node += nwarps) {
        float4 xv = x4[(size_t)node * 32 + lane];
        float4 a[NV];
        #pragma unroll
        for (int v = 0; v < NV; v++) {
            a[v].x = xv.x * vv[v][0].x + xv.y * vv[v][1].x + xv.z * vv[v][2].x + xv.w * vv[v][3].x;
            a[v].y = xv.x * vv[v][0].y + xv.y * vv[v][1].y + xv.z * vv[v][2].y + xv.w * vv[v][3].y;
            a[v].z = xv.x * vv[v][0].z + xv.y * vv[v][1].z + xv.z * vv[v][2].z + xv.w * vv[v][3].z;
            a[v].w = xv.x * vv[v][0].w + xv.y * vv[v][1].w + xv.z * vv[v][2].w + xv.w * vv[v][3].w;
        }
        #pragma unroll
        for (int off = 16; off; off >>= 1) {
            #pragma unroll
            for (int v = 0; v < NV; v++) {
                a[v].x += __shfl_xor_sync(0xffffffff, a[v].x, off);
                a[v].y += __shfl_xor_sync(0xffffffff, a[v].y, off);
                a[v].z += __shfl_xor_sync(0xffffffff, a[v].z, off);
                a[v].w += __shfl_xor_sync(0xffffffff, a[v].w, off);
            }
        }
        if (lane == 0) {
            #pragma unroll
            for (int v = 0; v < NV; v++)
                reinterpret_cast<float4*>(outs[v])[node] = a[v];
        }
    }
}

// ---------------- fused bias + leaky_relu(0.01) + projections ----------------
template <int NV>
__global__ void __launch_bounds__(256) bias_act_proj_kernel(
    float* __restrict__ y, const float* __restrict__ b1, const float* __restrict__ b2,
    const float* __restrict__ V,
    float* __restrict__ o0, float* __restrict__ o1, float* __restrict__ o2, int n)
{
    int lane   = threadIdx.x & 31;
    int warp   = (blockIdx.x * blockDim.x + threadIdx.x) >> 5;
    int nwarps = (gridDim.x * blockDim.x) >> 5;

    float4 bb = reinterpret_cast<const float4*>(b1)[lane];
    if (b2) {
        float4 t = reinterpret_cast<const float4*>(b2)[lane];
        bb.x += t.x; bb.y += t.y; bb.z += t.z; bb.w += t.w;
    }

    const float4* V4 = reinterpret_cast<const float4*>(V);
    float4 vv[NV][4];
    #pragma unroll
    for (int v = 0; v < NV; v++)
        #pragma unroll
        for (int q = 0; q < 4; q++)
            vv[v][q] = V4[v * 128 + lane * 4 + q];

    float* outs[3] = {o0, o1, o2};
    float4* y4 = reinterpret_cast<float4*>(y);

    for (int node = warp; node < n; node += nwarps) {
        float4 xv = y4[(size_t)node * 32 + lane];
        xv.x += bb.x; xv.y += bb.y; xv.z += bb.z; xv.w += bb.w;
        xv.x = fmaxf(xv.x, 0.01f * xv.x);
        xv.y = fmaxf(xv.y, 0.01f * xv.y);
        xv.z = fmaxf(xv.z, 0.01f * xv.z);
        xv.w = fmaxf(xv.w, 0.01f * xv.w);
        y4[(size_t)node * 32 + lane] = xv;

        float4 a[NV];
        #pragma unroll
        for (int v = 0; v < NV; v++) {
            a[v].x = xv.x * vv[v][0].x + xv.y * vv[v][1].x + xv.z * vv[v][2].x + xv.w * vv[v][3].x;
            a[v].y = xv.x * vv[v][0].y + xv.y * vv[v][1].y + xv.z * vv[v][2].y + xv.w * vv[v][3].y;
            a[v].z = xv.x * vv[v][0].z + xv.y * vv[v][1].z + xv.z * vv[v][2].z + xv.w * vv[v][3].z;
            a[v].w = xv.x * vv[v][0].w + xv.y * vv[v][1].w + xv.z * vv[v][2].w + xv.w * vv[v][3].w;
        }
        #pragma unroll
        for (int off = 16; off; off >>= 1) {
            #pragma unroll
            for (int v = 0; v < NV; v++) {
                a[v].x += __shfl_xor_sync(0xffffffff, a[v].x, off);
                a[v].y += __shfl_xor_sync(0xffffffff, a[v].y, off);
                a[v].z += __shfl_xor_sync(0xffffffff, a[v].z, off);
                a[v].w += __shfl_xor_sync(0xffffffff, a[v].w, off);
            }
        }
        if (lane == 0) {
            #pragma unroll
            for (int v = 0; v < NV; v++)
                reinterpret_cast<float4*>(outs[v])[node] = a[v];
        }
    }
}

// ---------------- fused multi-relation edge kernels ----------------
struct LgParams {
    const int*   ei[3];
    const float* AS[3];
    const float* AD[3];
    float*       EW[3];
    float*       Z[3];
};

__global__ void logits_multi_kernel(LgParams p, int E)
{
    int rel = blockIdx.y;
    int e = blockIdx.x * blockDim.x + threadIdx.x;
    if (e >= E) return;
    const int* ei = p.ei[rel];
    int src = ei[e];
    int dst = ei[E + e];
    float4 s = reinterpret_cast<const float4*>(p.AS[rel])[src];
    float4 d = reinterpret_cast<const float4*>(p.AD[rel])[dst];
    float4 w; float t;
    t = s.x + d.x; t = fmaxf(t, 0.2f * t); w.x = expf(t);
    t = s.y + d.y; t = fmaxf(t, 0.2f * t); w.y = expf(t);
    t = s.z + d.z; t = fmaxf(t, 0.2f * t); w.z = expf(t);
    t = s.w + d.w; t = fmaxf(t, 0.2f * t); w.w = expf(t);
    reinterpret_cast<float4*>(p.EW[rel])[e] = w;
    atomicAdd(reinterpret_cast<float4*>(p.Z[rel] + (size_t)dst * HH), w);
}

struct ScParams {
    const int*   ei[3];
    const float* h[3];
    const float* Z[3];
    const float* EW[3];
    float*       acc[3];
};

__global__ void scatter_multi_kernel(ScParams p, int E)
{
    int rel  = blockIdx.y;
    int e    = (blockIdx.x * blockDim.x + threadIdx.x) >> 5;
    int lane = threadIdx.x & 31;
    if (e >= E) return;
    const int* ei = p.ei[rel];
    int src = ei[e];
    int dst = ei[E + e];
    int h   = lane >> 3;
    float w = p.EW[rel][(size_t)e * HH + h];
    float z = p.Z[rel][(size_t)dst * HH + h];
    float alpha = w / (z + 1e-16f);
    float4 hv = *reinterpret_cast<const float4*>(p.h[rel] + (size_t)src * HD + lane * 4);
    float4 m  = make_float4(hv.x * alpha, hv.y * alpha, hv.z * alpha, hv.w * alpha);
    atomicAdd(reinterpret_cast<float4*>(p.acc[rel] + (size_t)dst * HD + lane * 4), m);
}

// ---------------- tf32 tensor-core GEMM v2 ----------------
// C[M,Nc] = A[M,128] @ B[128,Nc] (+bias). Block 128x128, 8 warps (2M x 4N),
// warp tile 64x32, mma.m16n8k8.tf32. B fragments SMEM-resident for full K
// (64KB, staged once); A staged per 32-K chunk (16KB) with register prefetch
// and rotated STS order (conflict-free A staging, <=2-way B staging).

__device__ __forceinline__ uint32_t f2tf32(float x) {
    uint32_t r; asm("cvt.rna.tf32.f32 %0, %1;" : "=r"(r) : "f"(x)); return r;
}

__device__ __forceinline__ void mma_tf32(float& c0, float& c1, float& c2, float& c3,
                                         uint32_t a0, uint32_t a1, uint32_t a2, uint32_t a3,
                                         uint32_t b0, uint32_t b1)
{
    asm volatile(
        "mma.sync.aligned.m16n8k8.row.col.f32.tf32.tf32.f32 "
        "{%0,%1,%2,%3}, {%4,%5,%6,%7}, {%8,%9}, {%0,%1,%2,%3};"
        : "+f"(c0), "+f"(c1), "+f"(c2), "+f"(c3)
        : "r"(a0), "r"(a1), "r"(a2), "r"(a3), "r"(b0), "r"(b1));
}

struct GemmBatch {
    const float* A[3];
    const float* B[3];
    float*       C[3];
    const float* bias;
    int M, Nc;
};

#define GEMM_SMEM_BYTES ((16384 + 4096) * 4)

template <bool ALIGNED>
__global__ void __launch_bounds__(256, 2) gemm_v2_kernel(GemmBatch p)
{
    extern __shared__ uint32_t smem_u[];
    uint32_t* Bf = smem_u;              // 16384 words: [k8(16)][n8(16)][lane*2+reg]
    uint32_t* Af = smem_u + 16384;      // 4096 words:  [k8c(4)][m16(8)][lane*4+reg]

    const float* A = p.A[blockIdx.z];
    const float* B = p.B[blockIdx.z];
    float*       C = p.C[blockIdx.z];
    const int M = p.M, Nc = p.Nc;

    const int tid  = threadIdx.x;
    const int lane = tid & 31;
    const int w    = tid >> 5;
    const int wm   = w & 1;
    const int wn   = w >> 1;
    const int m0   = blockIdx.x * 128;
    const int n0   = blockIdx.y * 128;

    // ---- stage B (full K=128) ----
    {
        int g    = (lane >> 3) & 3;     // k sub-row
        int cq3  = lane & 7;            // n-float4 sub
        #pragma unroll 4
        for (int it = 0; it < 16; it++) {
            int qg = it * 8 + (tid >> 5);          // 0..127
            int kr = (qg & 31) * 4 + g;            // 0..127
            int nf = (qg >> 5) * 8 + cq3;          // 0..31
            int gn = n0 + nf * 4;
            float4 v;
            if (ALIGNED) {
                v = *reinterpret_cast<const float4*>(B + (size_t)kr * Nc + gn);
            } else {
                v = make_float4(0.f, 0.f, 0.f, 0.f);
                if (gn + 0 < Nc) v.x = B[(size_t)kr * Nc + gn + 0];
                if (gn + 1 < Nc) v.y = B[(size_t)kr * Nc + gn + 1];
                if (gn + 2 < Nc) v.z = B[(size_t)kr * Nc + gn + 2];
                if (gn + 3 < Nc) v.w = B[(size_t)kr * Nc + gn + 3];
            }
            float vals[4] = {v.x, v.y, v.z, v.w};
            int k8  = kr >> 3;
            int reg = (kr >> 2) & 1;
            int kl  = kr & 3;
            #pragma unroll
            for (int s = 0; s < 4; s++) {
                int j  = (s + cq3) & 3;
                int n  = nf * 4 + j;
                int n8 = n >> 3;
                int bl = ((n & 7) << 2) + kl;
                Bf[(k8 * 16 + n8) * 64 + bl * 2 + reg] = f2tf32(vals[j]);
            }
        }
    }

    // A staging helpers
    const int gA   = lane >> 3;         // r sub-row (0..3)
    const int kcA  = lane & 7;          // k-float4 within chunk
    const int rotA = (gA + (kcA >> 1)) & 3;

    float4 pf[4];
    auto loadA = [&](int c) {
        #pragma unroll
        for (int it = 0; it < 4; it++) {
            int qg = it * 8 + (tid >> 5);          // 0..31
            int r  = qg * 4 + gA;                  // 0..127
            int gm = m0 + r;
            if (gm < M)
                pf[it] = *reinterpret_cast<const float4*>(A + (size_t)gm * 128 + c * 32 + kcA * 4);
            else
                pf[it] = make_float4(0.f, 0.f, 0.f, 0.f);
        }
    };
    auto storeA = [&]() {
        int k8c = kcA >> 1;
        int khi = kcA & 1;
        #pragma unroll
        for (int it = 0; it < 4; it++) {
            int qg = it * 8 + (tid >> 5);
            int r  = qg * 4 + gA;
            int reg = (khi << 1) | ((r >> 3) & 1);
            float vals[4] = {pf[it].x, pf[it].y, pf[it].z, pf[it].w};
            uint32_t* base = &Af[(k8c * 8 + (r >> 4)) * 128 + reg];
            #pragma unroll
            for (int s = 0; s < 4; s++) {
                int j = (s + rotA) & 3;
                base[(((r & 7) << 2) + j) * 4] = f2tf32(vals[j]);
            }
        }
    };

    float acc[4][4][4];
    #pragma unroll
    for (int i = 0; i < 4; i++)
        #pragma unroll
        for (int j = 0; j < 4; j++)
            #pragma unroll
            for (int q = 0; q < 4; q++) acc[i][j][q] = 0.f;

    loadA(0);
    storeA();
    __syncthreads();      // Bf + Af chunk0 ready

    for (int c = 0; c < 4; c++) {
        if (c < 3) loadA(c + 1);        // LDG overlapped with compute

        #pragma unroll
        for (int k8c = 0; k8c < 4; k8c++) {
            int k8g = c * 4 + k8c;
            uint32_t a[4][4];
            uint32_t b[4][2];
            #pragma unroll
            for (int i = 0; i < 4; i++) {
                uint4 t = *reinterpret_cast<uint4*>(&Af[(k8c * 8 + wm * 4 + i) * 128 + lane * 4]);
                a[i][0] = t.x; a[i][1] = t.y; a[i][2] = t.z; a[i][3] = t.w;
            }
            #pragma unroll
            for (int j = 0; j < 4; j++) {
                uint2 t = *reinterpret_cast<uint2*>(&Bf[(k8g * 16 + wn * 4 + j) * 64 + lane * 2]);
                b[j][0] = t.x; b[j][1] = t.y;
            }
            #pragma unroll
            for (int i = 0; i < 4; i++)
                #pragma unroll
                for (int j = 0; j < 4; j++)
                    mma_tf32(acc[i][j][0], acc[i][j][1], acc[i][j][2], acc[i][j][3],
                             a[i][0], a[i][1], a[i][2], a[i][3], b[j][0], b[j][1]);
        }

        if (c < 3) {
            __syncthreads();            // everyone done reading Af
            storeA();
            __syncthreads();            // next chunk ready
        }
    }

    // ---- epilogue ----
    const int gID = lane >> 2;
    const int tig = lane & 3;
    const float* bias = p.bias;
    #pragma unroll
    for (int i = 0; i < 4; i++) {
        int row0 = m0 + wm * 64 + i * 16 + gID;
        #pragma unroll
        for (int j = 0; j < 4; j++) {
            int col = n0 + wn * 32 + j * 8 + tig * 2;
            float bx = 0.f, by = 0.f;
            if (bias) {
                if (col < Nc)     bx = bias[col];
                if (col + 1 < Nc) by = bias[col + 1];
            }
            if (ALIGNED) {
                if (row0 < M) {
                    float2 o = make_float2(acc[i][j][0] + bx, acc[i][j][1] + by);
                    *reinterpret_cast<float2*>(C + (size_t)row0 * Nc + col) = o;
                }
                if (row0 + 8 < M) {
                    float2 o = make_float2(acc[i][j][2] + bx, acc[i][j][3] + by);
                    *reinterpret_cast<float2*>(C + (size_t)(row0 + 8) * Nc + col) = o;
                }
            } else {
                if (row0 < M) {
                    if (col < Nc)     C[(size_t)row0 * Nc + col]     = acc[i][j][0] + bx;
                    if (col + 1 < Nc) C[(size_t)row0 * Nc + col + 1] = acc[i][j][1] + by;
                }
                if (row0 + 8 < M) {
                    if (col < Nc)     C[(size_t)(row0 + 8) * Nc + col]     = acc[i][j][2] + bx;
                    if (col + 1 < Nc) C[(size_t)(row0 + 8) * Nc + col + 1] = acc[i][j][3] + by;
                }
            }
        }
    }
}

// ---------------- host launch ----------------
extern "C" void kernel_launch(void* const* d_in, const int* in_sizes, int n_in,
                              void* d_out, int out_size)
{
    const float* xs[2]   = {nullptr, nullptr}; int nx = 0;
    const int*   eis[3]  = {nullptr, nullptr, nullptr}; int ne = 0;
    const float* Ws[6]   = {}; int nw = 0;
    const float* attb[18]= {}; int na = 0;
    const float* linW = nullptr;
    const float* linb = nullptr;

    for (int i = 0; i < n_in; i++) {
        int s = in_sizes[i];
        if      (s == NN * DIN   && nx < 2)  xs[nx++]   = (const float*)d_in[i];
        else if (s == 2 * EE     && ne < 3)  eis[ne++]  = (const int*)d_in[i];
        else if (s == DIN * HD   && nw < 6)  Ws[nw++]   = (const float*)d_in[i];
        else if (s == HD         && na < 18) attb[na++] = (const float*)d_in[i];
        else if (s == HD * NOUT)             linW       = (const float*)d_in[i];
        else if (s == NOUT)                  linb       = (const float*)d_in[i];
    }
    if (nx != 2 || ne != 3 || nw != 6 || na != 18 || !linW || !linb) return;

    static bool attr_done = false;
    if (!attr_done) {
        cudaFuncSetAttribute(gemm_v2_kernel<true>,
                             cudaFuncAttributeMaxDynamicSharedMemorySize, GEMM_SMEM_BYTES);
        cudaFuncSetAttribute(gemm_v2_kernel<false>,
                             cudaFuncAttributeMaxDynamicSharedMemorySize, GEMM_SMEM_BYTES);
        attr_done = true;
    }

    float *pH, *pACC, *pP, *pZ, *pEW, *pV, *pLB2;
    cudaGetSymbolAddress((void**)&pH,   g_H);
    cudaGetSymbolAddress((void**)&pACC, g_ACC);
    cudaGetSymbolAddress((void**)&pP,   g_P);
    cudaGetSymbolAddress((void**)&pZ,   g_Z);
    cudaGetSymbolAddress((void**)&pEW,  g_EW);
    cudaGetSymbolAddress((void**)&pV,   g_V);
    cudaGetSymbolAddress((void**)&pLB2, g_LB2);

    const size_t FEAT = (size_t)NN * HD;
    float* H0  = pH;
    float* H1  = pH + FEAT;
    float* H2  = pH + 2 * FEAT;
    float* XP1 = pACC;
    float* XA1 = pACC + FEAT;
    float* XP2 = pACC + 2 * FEAT;
    float* P0 = pP + 0 * (size_t)NN * HH;
    float* P1 = pP + 1 * (size_t)NN * HH;
    float* P2 = pP + 2 * (size_t)NN * HH;
    float* P3 = pP + 3 * (size_t)NN * HH;
    float* P4 = pP + 4 * (size_t)NN * HH;
    float* P5 = pP + 5 * (size_t)NN * HH;
    float* Zs[5];
    for (int i = 0; i < 5; i++) Zs[i] = pZ + (size_t)i * NN * HH;
    float* EW0 = pEW;
    float* EW1 = pEW + (size_t)EE * HH;
    float* EW2 = pEW + 2 * (size_t)EE * HH;

    // memsets (not counted by ncu launch skip)
    cudaMemsetAsync(pACC, 0, 3 * FEAT * sizeof(float));
    cudaMemsetAsync(pZ,   0, 5 * (size_t)NN * HH * sizeof(float));

    // ---- launch 0: prep ----
    PrepParams pp;
    pp.W[0] = Ws[0]; pp.att[0] = attb[0];   // as0_c
    pp.W[1] = Ws[0]; pp.att[1] = attb[1];   // ad0_c
    pp.W[2] = Ws[1]; pp.att[2] = attb[4];   // ad0_w
    pp.W[3] = Ws[2]; pp.att[3] = attb[6];   // as0_wb
    pp.W[4] = Ws[1]; pp.att[4] = attb[3];   // as0_w
    pp.W[5] = Ws[2]; pp.att[5] = attb[7];   // ad0_wb
    pp.W[6] = Ws[3]; pp.att[6] = attb[9];   // as1_c
    pp.W[7] = Ws[3]; pp.att[7] = attb[10];  // ad1_c
    pp.W[8] = Ws[4]; pp.att[8] = attb[13];  // ad1_w
    pp.W[9] = Ws[4]; pp.att[9] = attb[12];  // as1_w
    pp.V = pV; pp.linW = linW; pp.linb = linb;
    pp.bc = attb[11]; pp.bw = attb[14]; pp.linb2 = pLB2;
    prep_all_kernel<<<12, 256>>>(pp);

    const dim3 ggrid((NN + 127) / 128, 1, 3);

    // ---- launch 1: layer-0 GEMMs (3 relations) ----
    GemmBatch g0;
    g0.A[0] = xs[0]; g0.B[0] = Ws[0]; g0.C[0] = H0;   // cites: xp @ W0_c
    g0.A[1] = xs[1]; g0.B[1] = Ws[1]; g0.C[1] = H1;   // writes: xa @ W0_w
    g0.A[2] = xs[0]; g0.B[2] = Ws[2]; g0.C[2] = H2;   // written_by: xp @ W0_wb
    g0.bias = nullptr; g0.M = NN; g0.Nc = HD;
    gemm_v2_kernel<true><<<ggrid, 256, GEMM_SMEM_BYTES>>>(g0);

    // ---- launches 2,3: layer-0 projections ----
    proj_multi_kernel<4><<<1024, 256>>>(xs[0], pV,              P0, P1, P2, P3, NN);
    proj_multi_kernel<2><<<1024, 256>>>(xs[1], pV + 4 * 512,    P4, P5, nullptr, nullptr, NN);

    // ---- launch 4: layer-0 logits (3 relations) ----
    LgParams lg0;
    lg0.ei[0] = eis[0]; lg0.AS[0] = P0; lg0.AD[0] = P1; lg0.EW[0] = EW0; lg0.Z[0] = Zs[0];
    lg0.ei[1] = eis[1]; lg0.AS[1] = P4; lg0.AD[1] = P2; lg0.EW[1] = EW1; lg0.Z[1] = Zs[1];
    lg0.ei[2] = eis[2]; lg0.AS[2] = P3; lg0.AD[2] = P5; lg0.EW[2] = EW2; lg0.Z[2] = Zs[2];
    logits_multi_kernel<<<dim3((EE + 255) / 256, 3), 256>>>(lg0, EE);

    // ---- launch 5 (ncu target): layer-0 scatter (3 relations) ----
    ScParams sc0;
    sc0.ei[0] = eis[0]; sc0.h[0] = H0; sc0.Z[0] = Zs[0]; sc0.EW[0] = EW0; sc0.acc[0] = XP1;
    sc0.ei[1] = eis[1]; sc0.h[1] = H1; sc0.Z[1] = Zs[1]; sc0.EW[1] = EW1; sc0.acc[1] = XP1;
    sc0.ei[2] = eis[2]; sc0.h[2] = H2; sc0.Z[2] = Zs[2]; sc0.EW[2] = EW2; sc0.acc[2] = XA1;
    scatter_multi_kernel<<<dim3((EE * 32 + 255) / 256, 3), 256>>>(sc0, EE);

    // ---- launches 6,7: fused bias+act+proj (layer-1 inputs) ----
    bias_act_proj_kernel<3><<<1024, 256>>>(XP1, attb[2], attb[5], pV + 6 * 512,
                                           P0, P1, P2, NN);
    bias_act_proj_kernel<1><<<1024, 256>>>(XA1, attb[8], nullptr, pV + 9 * 512,
                                           P4, nullptr, nullptr, NN);

    // ---- launch 8: layer-1 GEMMs (2 relations) ----
    GemmBatch g1;
    g1.A[0] = XP1; g1.B[0] = Ws[3]; g1.C[0] = H0;     // cites: xp1 @ W1_c
    g1.A[1] = XA1; g1.B[1] = Ws[4]; g1.C[1] = H1;     // writes: xa1 @ W1_w
    g1.A[2] = XP1; g1.B[2] = Ws[3]; g1.C[2] = H0;     // unused
    g1.bias = nullptr; g1.M = NN; g1.Nc = HD;
    gemm_v2_kernel<true><<<dim3((NN + 127) / 128, 1, 2), 256, GEMM_SMEM_BYTES>>>(g1);

    // ---- launch 9: layer-1 logits ----
    LgParams lg1;
    lg1.ei[0] = eis[0]; lg1.AS[0] = P0; lg1.AD[0] = P1; lg1.EW[0] = EW0; lg1.Z[0] = Zs[3];
    lg1.ei[1] = eis[1]; lg1.AS[1] = P4; lg1.AD[1] = P2; lg1.EW[1] = EW1; lg1.Z[1] = Zs[4];
    lg1.ei[2] = eis[0]; lg1.AS[2] = P0; lg1.AD[2] = P1; lg1.EW[2] = EW0; lg1.Z[2] = Zs[3];
    logits_multi_kernel<<<dim3((EE + 255) / 256, 2), 256>>>(lg1, EE);

    // ---- launch 10: layer-1 scatter ----
    ScParams sc1;
    sc1.ei[0] = eis[0]; sc1.h[0] = H0; sc1.Z[0] = Zs[3]; sc1.EW[0] = EW0; sc1.acc[0] = XP2;
    sc1.ei[1] = eis[1]; sc1.h[1] = H1; sc1.Z[1] = Zs[4]; sc1.EW[1] = EW1; sc1.acc[1] = XP2;
    sc1.ei[2] = eis[0]; sc1.h[2] = H0; sc1.Z[2] = Zs[3]; sc1.EW[2] = EW0; sc1.acc[2] = XP2;
    scatter_multi_kernel<<<dim3((EE * 32 + 255) / 256, 2), 256>>>(sc1, EE);

    // ---- launch 11: classifier (bias folded: linb2 = linb + (b1_c+b1_w)@linW) ----
    GemmBatch gc;
    gc.A[0] = XP2; gc.B[0] = linW; gc.C[0] = (float*)d_out;
    gc.A[1] = XP2; gc.B[1] = linW; gc.C[1] = (float*)d_out;
    gc.A[2] = XP2; gc.B[2] = linW; gc.C[2] = (float*)d_out;
    gc.bias = pLB2; gc.M = NN; gc.Nc = NOUT;
    gemm_v2_kernel<false><<<dim3((NN + 127) / 128, (NOUT + 127) / 128, 1), 256, GEMM_SMEM_BYTES>>>(gc);
}

// round 5
// speedup vs baseline: 2.1169x; 2.1169x over previous
#include <cuda_runtime.h>
#include <cstdint>

// ---------------- problem constants ----------------
#define NN      100000
#define EE      250000
#define HH      4
#define HD      128
#define NOUT    349

// ---------------- device scratch ----------------
__device__ float g_H  [3ll * NN * HD];   // per-relation h = x@W
__device__ float g_ACC[5ll * NN * HD];   // unnormalized message sums
__device__ float g_X  [2ll * NN * HD];   // XP1, XA1
__device__ float g_P  [6ll * NN * HH];   // attention logit buffers [n*4+h]
__device__ float g_Z  [5ll * NN * HH];   // softmax denominators
__device__ float g_V  [3 * HD * HH];     // W·att_d vectors (3 needed)
__device__ float g_LB2[NOUT];            // folded classifier bias

// ---------------- prep: 3 V vectors + folded classifier bias ----------------
struct PrepParams {
    const float* W[3];
    const float* att[3];
    float* V;
    const float* linW;
    const float* linb;
    const float* bc;   // b1_c
    const float* bw;   // b1_w
    float* linb2;
};

__global__ void prep_all_kernel(PrepParams p)
{
    int b = blockIdx.x;
    if (b < 3) {
        int k = threadIdx.x;
        if (k >= HD) return;
        const float* W   = p.W[b];
        const float* att = p.att[b];
        #pragma unroll
        for (int h = 0; h < HH; h++) {
            float s = 0.f;
            #pragma unroll
            for (int c = 0; c < 32; c++)
                s += W[k * HD + h * 32 + c] * att[h * 32 + c];
            p.V[b * (HD * HH) + k * HH + h] = s;
        }
    } else {
        int o = (b - 3) * 256 + threadIdx.x;
        if (o >= NOUT) return;
        float s = p.linb[o];
        #pragma unroll 4
        for (int j = 0; j < HD; j++)
            s += (p.bc[j] + p.bw[j]) * p.linW[(size_t)j * NOUT + o];
        p.linb2[o] = s;
    }
}

// ---------------- dst-side projections (V-trick), batched via blockIdx.y ----
struct ProjP {
    const float* x[2];
    const float* V[2];
    float*       out[2];
};

__global__ void __launch_bounds__(256) proj_dst_kernel(ProjP p, int n)
{
    int s = blockIdx.y;
    const float* x = p.x[s];
    const float* V = p.V[s];
    float* out = p.out[s];

    int lane   = threadIdx.x & 31;
    int warp   = (blockIdx.x * blockDim.x + threadIdx.x) >> 5;
    int nwarps = (gridDim.x * blockDim.x) >> 5;

    const float4* V4 = reinterpret_cast<const float4*>(V);
    float4 v0 = V4[lane * 4 + 0];
    float4 v1 = V4[lane * 4 + 1];
    float4 v2 = V4[lane * 4 + 2];
    float4 v3 = V4[lane * 4 + 3];

    const float4* x4 = reinterpret_cast<const float4*>(x);
    for (int node = warp; node < n; node += nwarps) {
        float4 xv = x4[(size_t)node * 32 + lane];
        float4 a;
        a.x = xv.x * v0.x + xv.y * v1.x + xv.z * v2.x + xv.w * v3.x;
        a.y = xv.x * v0.y + xv.y * v1.y + xv.z * v2.y + xv.w * v3.y;
        a.z = xv.x * v0.z + xv.y * v1.z + xv.z * v2.z + xv.w * v3.z;
        a.w = xv.x * v0.w + xv.y * v1.w + xv.z * v2.w + xv.w * v3.w;
        #pragma unroll
        for (int off = 16; off; off >>= 1) {
            a.x += __shfl_xor_sync(0xffffffff, a.x, off);
            a.y += __shfl_xor_sync(0xffffffff, a.y, off);
            a.z += __shfl_xor_sync(0xffffffff, a.z, off);
            a.w += __shfl_xor_sync(0xffffffff, a.w, off);
        }
        if (lane == 0)
            reinterpret_cast<float4*>(out)[node] = a;
    }
}

// ---------------- fused edge kernel: exp + Z + message scatter -------------
struct ScP {
    const int*   ei[3];
    const float* h[3];
    const float* AS[3];
    const float* AD[3];
    float*       acc[3];
    float*       Z[3];
};

__global__ void scatter_kernel(ScP p, int E)
{
    int rel  = blockIdx.y;
    int e    = (blockIdx.x * blockDim.x + threadIdx.x) >> 5;
    int lane = threadIdx.x & 31;
    if (e >= E) return;
    const int* ei = p.ei[rel];
    int src = ei[e];
    int dst = ei[E + e];
    int hh  = lane >> 3;

    float as = p.AS[rel][src * HH + hh];
    float ad = p.AD[rel][dst * HH + hh];
    float t  = as + ad;
    t = fmaxf(t, 0.2f * t);
    float w = __expf(t);

    float4 hv = *reinterpret_cast<const float4*>(p.h[rel] + (size_t)src * HD + lane * 4);
    float4 m  = make_float4(hv.x * w, hv.y * w, hv.z * w, hv.w * w);
    atomicAdd(reinterpret_cast<float4*>(p.acc[rel] + (size_t)dst * HD + lane * 4), m);
    if ((lane & 7) == 0)
        atomicAdd(p.Z[rel] + (size_t)dst * HH + hh, w);
}

// ---------------- combine: normalize + bias + act (+ dst proj) -------------
template <int NACC, int NV>
__global__ void __launch_bounds__(256) combine_kernel(
    const float* __restrict__ A0, const float* __restrict__ Z0,
    const float* __restrict__ A1, const float* __restrict__ Z1,
    const float* __restrict__ b1, const float* __restrict__ b2,
    const float* __restrict__ V,
    float* __restrict__ X, float* __restrict__ P, int n)
{
    int lane   = threadIdx.x & 31;
    int warp   = (blockIdx.x * blockDim.x + threadIdx.x) >> 5;
    int nwarps = (gridDim.x * blockDim.x) >> 5;
    int hh     = lane >> 3;

    float4 bb = reinterpret_cast<const float4*>(b1)[lane];
    if (NACC == 2) {
        float4 t = reinterpret_cast<const float4*>(b2)[lane];
        bb.x += t.x; bb.y += t.y; bb.z += t.z; bb.w += t.w;
    }

    float4 v0, v1, v2, v3;
    if (NV) {
        const float4* V4 = reinterpret_cast<const float4*>(V);
        v0 = V4[lane * 4 + 0];
        v1 = V4[lane * 4 + 1];
        v2 = V4[lane * 4 + 2];
        v3 = V4[lane * 4 + 3];
    }

    for (int node = warp; node < n; node += nwarps) {
        float i0 = 1.f / (Z0[(size_t)node * HH + hh] + 1e-16f);
        float4 xv = *reinterpret_cast<const float4*>(A0 + (size_t)node * HD + lane * 4);
        xv.x *= i0; xv.y *= i0; xv.z *= i0; xv.w *= i0;
        if (NACC == 2) {
            float i1 = 1.f / (Z1[(size_t)node * HH + hh] + 1e-16f);
            float4 t = *reinterpret_cast<const float4*>(A1 + (size_t)node * HD + lane * 4);
            xv.x += t.x * i1; xv.y += t.y * i1; xv.z += t.z * i1; xv.w += t.w * i1;
        }
        xv.x += bb.x; xv.y += bb.y; xv.z += bb.z; xv.w += bb.w;
        xv.x = fmaxf(xv.x, 0.01f * xv.x);
        xv.y = fmaxf(xv.y, 0.01f * xv.y);
        xv.z = fmaxf(xv.z, 0.01f * xv.z);
        xv.w = fmaxf(xv.w, 0.01f * xv.w);
        reinterpret_cast<float4*>(X)[(size_t)node * 32 + lane] = xv;

        if (NV) {
            float4 a;
            a.x = xv.x * v0.x + xv.y * v1.x + xv.z * v2.x + xv.w * v3.x;
            a.y = xv.x * v0.y + xv.y * v1.y + xv.z * v2.y + xv.w * v3.y;
            a.z = xv.x * v0.z + xv.y * v1.z + xv.z * v2.z + xv.w * v3.z;
            a.w = xv.x * v0.w + xv.y * v1.w + xv.z * v2.w + xv.w * v3.w;
            #pragma unroll
            for (int off = 16; off; off >>= 1) {
                a.x += __shfl_xor_sync(0xffffffff, a.x, off);
                a.y += __shfl_xor_sync(0xffffffff, a.y, off);
                a.z += __shfl_xor_sync(0xffffffff, a.z, off);
                a.w += __shfl_xor_sync(0xffffffff, a.w, off);
            }
            if (lane == 0)
                reinterpret_cast<float4*>(P)[node] = a;
        }
    }
}

// ---------------- tf32 tensor-core GEMM v3 ----------------
// C[M,Nc] = A[M,128] @ B[128,Nc] (+bias), K=128, chunks of 32.
// Block 128x128, 8 warps (2M x 4N), warp tile 64x32, mma.m16n8k8.tf32.
// Fragment-major smem, rotated stores, 32KB static smem, no reg prefetch.
// Epilogue optionally computes per-head attention dots (a_s, a_d) from acc.
// AMODE=1: A rows built on the fly as A0/Z0 + A1/Z1 (per-head normalize).

__device__ __forceinline__ uint32_t f2tf32(float x) {
    uint32_t r; asm("cvt.rna.tf32.f32 %0, %1;" : "=r"(r) : "f"(x)); return r;
}

__device__ __forceinline__ void mma_tf32(float& c0, float& c1, float& c2, float& c3,
                                         uint32_t a0, uint32_t a1, uint32_t a2, uint32_t a3,
                                         uint32_t b0, uint32_t b1)
{
    asm volatile(
        "mma.sync.aligned.m16n8k8.row.col.f32.tf32.tf32.f32 "
        "{%0,%1,%2,%3}, {%4,%5,%6,%7}, {%8,%9}, {%0,%1,%2,%3};"
        : "+f"(c0), "+f"(c1), "+f"(c2), "+f"(c3)
        : "r"(a0), "r"(a1), "r"(a2), "r"(a3), "r"(b0), "r"(b1));
}

struct GemmZ {
    const float* A;
    const float* A1;     // AMODE1 second acc
    const float* Za;     // AMODE1 denominators
    const float* Zb;
    const float* B;
    float*       C;
    const float* attS;   // epilogue dot vectors (may be null)
    const float* attD;
    float*       PS;
    float*       PD;
};
struct GemmP {
    GemmZ z[3];
    const float* bias;
    int M, Nc;
};

template <int AMODE, bool ALIGNED>
__global__ void __launch_bounds__(256, 2) gemm_v3_kernel(GemmP p)
{
    __shared__ uint32_t Af[4096];   // [k8c(4)][m16(8)][lane*4+reg]
    __shared__ uint32_t Bf[4096];   // [k8c(4)][n8(16)][lane*2+reg]

    const GemmZ zp = p.z[blockIdx.z];
    const int M = p.M, Nc = p.Nc;

    const int tid  = threadIdx.x;
    const int lane = tid & 31;
    const int w    = tid >> 5;
    const int wm   = w & 1;
    const int wn   = w >> 1;
    const int m0   = blockIdx.x * 128;
    const int n0   = blockIdx.y * 128;

    const int gA   = lane >> 3;      // 0..3
    const int kcA  = lane & 7;       // 0..7
    const int rotA = (gA + (kcA >> 1)) & 3;

    float acc[4][4][4];
    #pragma unroll
    for (int i = 0; i < 4; i++)
        #pragma unroll
        for (int j = 0; j < 4; j++)
            #pragma unroll
            for (int q = 0; q < 4; q++) acc[i][j][q] = 0.f;

    for (int c = 0; c < 4; c++) {
        // ---- stage A chunk (128 rows x 32 k) ----
        {
            int k8c = kcA >> 1;
            int khi = kcA & 1;
            #pragma unroll
            for (int it = 0; it < 4; it++) {
                int qg = it * 8 + w;
                int r  = qg * 4 + gA;
                int gm = m0 + r;
                float4 v = make_float4(0.f, 0.f, 0.f, 0.f);
                if (gm < M) {
                    if (AMODE == 0) {
                        v = *reinterpret_cast<const float4*>(zp.A + (size_t)gm * 128 + c * 32 + kcA * 4);
                    } else {
                        float ia = 1.f / (zp.Za[(size_t)gm * HH + c] + 1e-16f);
                        float ib = 1.f / (zp.Zb[(size_t)gm * HH + c] + 1e-16f);
                        float4 u0 = *reinterpret_cast<const float4*>(zp.A  + (size_t)gm * 128 + c * 32 + kcA * 4);
                        float4 u1 = *reinterpret_cast<const float4*>(zp.A1 + (size_t)gm * 128 + c * 32 + kcA * 4);
                        v.x = u0.x * ia + u1.x * ib;
                        v.y = u0.y * ia + u1.y * ib;
                        v.z = u0.z * ia + u1.z * ib;
                        v.w = u0.w * ia + u1.w * ib;
                    }
                }
                int reg = (khi << 1) | ((r >> 3) & 1);
                uint32_t* base = &Af[((k8c << 3) + (r >> 4)) * 128 + reg];
                float vals[4] = {v.x, v.y, v.z, v.w};
                #pragma unroll
                for (int s = 0; s < 4; s++) {
                    int j = (s + rotA) & 3;
                    base[(((r & 7) << 2) + j) << 2] = f2tf32(vals[j]);
                }
            }
        }
        // ---- stage B chunk (32 k-rows x 128 cols) ----
        {
            #pragma unroll
            for (int it = 0; it < 4; it++) {
                int qg  = it * 8 + w;                 // 0..31
                int krl = (qg & 7) * 4 + gA;          // 0..31
                int kr  = c * 32 + krl;
                int nf  = (qg >> 3) * 8 + kcA;        // 0..31
                int gn  = n0 + nf * 4;
                float4 v;
                if (ALIGNED) {
                    v = *reinterpret_cast<const float4*>(zp.B + (size_t)kr * Nc + gn);
                } else {
                    v = make_float4(0.f, 0.f, 0.f, 0.f);
                    if (gn + 0 < Nc) v.x = zp.B[(size_t)kr * Nc + gn + 0];
                    if (gn + 1 < Nc) v.y = zp.B[(size_t)kr * Nc + gn + 1];
                    if (gn + 2 < Nc) v.z = zp.B[(size_t)kr * Nc + gn + 2];
                    if (gn + 3 < Nc) v.w = zp.B[(size_t)kr * Nc + gn + 3];
                }
                int k8c = krl >> 3;
                int reg = (krl >> 2) & 1;
                int kl  = krl & 3;
                float vals[4] = {v.x, v.y, v.z, v.w};
                #pragma unroll
                for (int s = 0; s < 4; s++) {
                    int j = (s + kcA) & 3;
                    int n = nf * 4 + j;
                    Bf[((k8c << 4) + (n >> 3)) * 64 + ((((n & 7) << 2) + kl) << 1) + reg] = f2tf32(vals[j]);
                }
            }
        }
        __syncthreads();

        // ---- compute 4 k8 steps ----
        #pragma unroll
        for (int k8c = 0; k8c < 4; k8c++) {
            uint32_t a[4][4];
            uint32_t b[4][2];
            #pragma unroll
            for (int i = 0; i < 4; i++) {
                uint4 t = *reinterpret_cast<uint4*>(&Af[((k8c << 3) + wm * 4 + i) * 128 + (lane << 2)]);
                a[i][0] = t.x; a[i][1] = t.y; a[i][2] = t.z; a[i][3] = t.w;
            }
            #pragma unroll
            for (int j = 0; j < 4; j++) {
                uint2 t = *reinterpret_cast<uint2*>(&Bf[((k8c << 4) + wn * 4 + j) * 64 + (lane << 1)]);
                b[j][0] = t.x; b[j][1] = t.y;
            }
            #pragma unroll
            for (int i = 0; i < 4; i++)
                #pragma unroll
                for (int j = 0; j < 4; j++)
                    mma_tf32(acc[i][j][0], acc[i][j][1], acc[i][j][2], acc[i][j][3],
                             a[i][0], a[i][1], a[i][2], a[i][3], b[j][0], b[j][1]);
        }
        if (c < 3) __syncthreads();
    }

    // ---- epilogue: C write ----
    const int gID = lane >> 2;
    const int tig = lane & 3;
    const float* bias = p.bias;
    #pragma unroll
    for (int i = 0; i < 4; i++) {
        int row0 = m0 + wm * 64 + i * 16 + gID;
        #pragma unroll
        for (int j = 0; j < 4; j++) {
            int col = n0 + wn * 32 + j * 8 + tig * 2;
            float bx = 0.f, by = 0.f;
            if (bias) {
                if (col < Nc)     bx = bias[col];
                if (col + 1 < Nc) by = bias[col + 1];
            }
            if (ALIGNED) {
                if (row0 < M) {
                    float2 o = make_float2(acc[i][j][0] + bx, acc[i][j][1] + by);
                    *reinterpret_cast<float2*>(zp.C + (size_t)row0 * Nc + col) = o;
                }
                if (row0 + 8 < M) {
                    float2 o = make_float2(acc[i][j][2] + bx, acc[i][j][3] + by);
                    *reinterpret_cast<float2*>(zp.C + (size_t)(row0 + 8) * Nc + col) = o;
                }
            } else {
                if (row0 < M) {
                    if (col < Nc)     zp.C[(size_t)row0 * Nc + col]     = acc[i][j][0] + bx;
                    if (col + 1 < Nc) zp.C[(size_t)row0 * Nc + col + 1] = acc[i][j][1] + by;
                }
                if (row0 + 8 < M) {
                    if (col < Nc)     zp.C[(size_t)(row0 + 8) * Nc + col]     = acc[i][j][2] + bx;
                    if (col + 1 < Nc) zp.C[(size_t)(row0 + 8) * Nc + col + 1] = acc[i][j][3] + by;
                }
            }
        }
    }

    // ---- epilogue: attention dots a = h . att (head == warp column wn) ----
    if (AMODE == 0 && zp.attS) {
        bool hasD = (zp.attD != nullptr);
        float aS[4][2], aD[4][2];
        #pragma unroll
        for (int j = 0; j < 4; j++) {
            int cc = wn * 32 + j * 8 + tig * 2;
            aS[j][0] = zp.attS[cc];
            aS[j][1] = zp.attS[cc + 1];
            if (hasD) { aD[j][0] = zp.attD[cc]; aD[j][1] = zp.attD[cc + 1]; }
        }
        #pragma unroll
        for (int i = 0; i < 4; i++) {
            float s0 = 0.f, s1 = 0.f, d0 = 0.f, d1 = 0.f;
            #pragma unroll
            for (int j = 0; j < 4; j++) {
                s0 += acc[i][j][0] * aS[j][0] + acc[i][j][1] * aS[j][1];
                s1 += acc[i][j][2] * aS[j][0] + acc[i][j][3] * aS[j][1];
                if (hasD) {
                    d0 += acc[i][j][0] * aD[j][0] + acc[i][j][1] * aD[j][1];
                    d1 += acc[i][j][2] * aD[j][0] + acc[i][j][3] * aD[j][1];
                }
            }
            s0 += __shfl_xor_sync(0xffffffff, s0, 1); s0 += __shfl_xor_sync(0xffffffff, s0, 2);
            s1 += __shfl_xor_sync(0xffffffff, s1, 1); s1 += __shfl_xor_sync(0xffffffff, s1, 2);
            if (hasD) {
                d0 += __shfl_xor_sync(0xffffffff, d0, 1); d0 += __shfl_xor_sync(0xffffffff, d0, 2);
                d1 += __shfl_xor_sync(0xffffffff, d1, 1); d1 += __shfl_xor_sync(0xffffffff, d1, 2);
            }
            if (tig == 0) {
                int r0 = m0 + wm * 64 + i * 16 + gID;
                if (r0 < M)     zp.PS[(size_t)r0 * HH + wn]       = s0;
                if (r0 + 8 < M) zp.PS[(size_t)(r0 + 8) * HH + wn] = s1;
                if (hasD) {
                    if (r0 < M)     zp.PD[(size_t)r0 * HH + wn]       = d0;
                    if (r0 + 8 < M) zp.PD[(size_t)(r0 + 8) * HH + wn] = d1;
                }
            }
        }
    }
}

// ---------------- host launch ----------------
extern "C" void kernel_launch(void* const* d_in, const int* in_sizes, int n_in,
                              void* d_out, int out_size)
{
    const float* xs[2]   = {nullptr, nullptr}; int nx = 0;
    const int*   eis[3]  = {nullptr, nullptr, nullptr}; int ne = 0;
    const float* Ws[6]   = {}; int nw = 0;
    const float* attb[18]= {}; int na = 0;
    const float* linW = nullptr;
    const float* linb = nullptr;

    for (int i = 0; i < n_in; i++) {
        int s = in_sizes[i];
        if      (s == NN * HD    && nx < 2)  xs[nx++]   = (const float*)d_in[i];
        else if (s == 2 * EE     && ne < 3)  eis[ne++]  = (const int*)d_in[i];
        else if (s == HD * HD    && nw < 6)  Ws[nw++]   = (const float*)d_in[i];
        else if (s == HD         && na < 18) attb[na++] = (const float*)d_in[i];
        else if (s == HD * NOUT)             linW       = (const float*)d_in[i];
        else if (s == NOUT)                  linb       = (const float*)d_in[i];
    }
    if (nx != 2 || ne != 3 || nw != 6 || na != 18 || !linW || !linb) return;

    float *pH, *pACC, *pX, *pP, *pZ, *pV, *pLB2;
    cudaGetSymbolAddress((void**)&pH,   g_H);
    cudaGetSymbolAddress((void**)&pACC, g_ACC);
    cudaGetSymbolAddress((void**)&pX,   g_X);
    cudaGetSymbolAddress((void**)&pP,   g_P);
    cudaGetSymbolAddress((void**)&pZ,   g_Z);
    cudaGetSymbolAddress((void**)&pV,   g_V);
    cudaGetSymbolAddress((void**)&pLB2, g_LB2);

    const size_t FEAT = (size_t)NN * HD;
    float* H0  = pH;
    float* H1  = pH + FEAT;
    float* H2  = pH + 2 * FEAT;
    float* ACC0 = pACC;
    float* ACC1 = pACC + FEAT;
    float* ACC2 = pACC + 2 * FEAT;
    float* ACC3 = pACC + 3 * FEAT;
    float* ACC4 = pACC + 4 * FEAT;
    float* XP1 = pX;
    float* XA1 = pX + FEAT;
    float* Pb[6];
    for (int i = 0; i < 6; i++) Pb[i] = pP + (size_t)i * NN * HH;
    float* Zs[5];
    for (int i = 0; i < 5; i++) Zs[i] = pZ + (size_t)i * NN * HH;
    float* v0 = pV;               // W0_w  . ad0_w   (paper-side dst for writes)
    float* v1 = pV + 512;         // W0_wb . ad0_wb  (author-side dst for written_by)
    float* v2 = pV + 1024;        // W1_w  . ad1_w   (paper-side dst for L1 writes)

    // launches 0..2: memsets (count toward ncu -s; gemm L0 lands at index 5)
    cudaMemsetAsync(pACC, 0, 3 * FEAT * sizeof(float));
    cudaMemsetAsync(pACC + 3 * FEAT, 0, 2 * FEAT * sizeof(float));
    cudaMemsetAsync(pZ,   0, 5 * (size_t)NN * HH * sizeof(float));

    // launch 3: prep
    PrepParams pp;
    pp.W[0] = Ws[1]; pp.att[0] = attb[4];    // ad0_w
    pp.W[1] = Ws[2]; pp.att[1] = attb[7];    // ad0_wb
    pp.W[2] = Ws[4]; pp.att[2] = attb[13];   // ad1_w
    pp.V = pV; pp.linW = linW; pp.linb = linb;
    pp.bc = attb[11]; pp.bw = attb[14]; pp.linb2 = pLB2;
    prep_all_kernel<<<5, 256>>>(pp);

    // launch 4: dst-side projections for L0 (writes, written_by)
    ProjP prj;
    prj.x[0] = xs[0]; prj.V[0] = v0; prj.out[0] = Pb[3];   // AD_w0  (papers)
    prj.x[1] = xs[1]; prj.V[1] = v1; prj.out[1] = Pb[5];   // AD_wb0 (authors)
    proj_dst_kernel<<<dim3(512, 2), 256>>>(prj, NN);

    // launch 5 (ncu target): L0 GEMMs + epilogue attention dots
    GemmP g0 = {};
    g0.z[0] = {xs[0], nullptr, nullptr, nullptr, Ws[0], H0, attb[0], attb[1], Pb[0], Pb[1]};
    g0.z[1] = {xs[1], nullptr, nullptr, nullptr, Ws[1], H1, attb[3], nullptr, Pb[2], nullptr};
    g0.z[2] = {xs[0], nullptr, nullptr, nullptr, Ws[2], H2, attb[6], nullptr, Pb[4], nullptr};
    g0.bias = nullptr; g0.M = NN; g0.Nc = HD;
    gemm_v3_kernel<0, true><<<dim3((NN + 127) / 128, 1, 3), 256>>>(g0);

    // launch 6: L0 scatter (fused exp + Z + messages)
    ScP s0;
    s0.ei[0] = eis[0]; s0.h[0] = H0; s0.AS[0] = Pb[0]; s0.AD[0] = Pb[1]; s0.acc[0] = ACC0; s0.Z[0] = Zs[0];
    s0.ei[1] = eis[1]; s0.h[1] = H1; s0.AS[1] = Pb[2]; s0.AD[1] = Pb[3]; s0.acc[1] = ACC1; s0.Z[1] = Zs[1];
    s0.ei[2] = eis[2]; s0.h[2] = H2; s0.AS[2] = Pb[4]; s0.AD[2] = Pb[5]; s0.acc[2] = ACC2; s0.Z[2] = Zs[2];
    scatter_kernel<<<dim3((EE * 32 + 255) / 256, 3), 256>>>(s0, EE);

    // launches 7,8: combine -> XP1 (with fused L1 dst proj), XA1
    combine_kernel<2, 1><<<1024, 256>>>(ACC0, Zs[0], ACC1, Zs[1],
                                        attb[2], attb[5], v2, XP1, Pb[3], NN);
    combine_kernel<1, 0><<<1024, 256>>>(ACC2, Zs[2], nullptr, nullptr,
                                        attb[8], nullptr, nullptr, XA1, nullptr, NN);

    // launch 9: L1 GEMMs + epilogue dots
    GemmP g1 = {};
    g1.z[0] = {XP1, nullptr, nullptr, nullptr, Ws[3], H0, attb[9],  attb[10], Pb[0], Pb[1]};
    g1.z[1] = {XA1, nullptr, nullptr, nullptr, Ws[4], H1, attb[12], nullptr,  Pb[2], nullptr};
    g1.z[2] = g1.z[0];
    g1.bias = nullptr; g1.M = NN; g1.Nc = HD;
    gemm_v3_kernel<0, true><<<dim3((NN + 127) / 128, 1, 2), 256>>>(g1);

    // launch 10: L1 scatter
    ScP s1;
    s1.ei[0] = eis[0]; s1.h[0] = H0; s1.AS[0] = Pb[0]; s1.AD[0] = Pb[1]; s1.acc[0] = ACC3; s1.Z[0] = Zs[3];
    s1.ei[1] = eis[1]; s1.h[1] = H1; s1.AS[1] = Pb[2]; s1.AD[1] = Pb[3]; s1.acc[1] = ACC4; s1.Z[1] = Zs[4];
    s1.ei[2] = s1.ei[0]; s1.h[2] = s1.h[0]; s1.AS[2] = s1.AS[0]; s1.AD[2] = s1.AD[0];
    s1.acc[2] = ACC3; s1.Z[2] = Zs[3];
    scatter_kernel<<<dim3((EE * 32 + 255) / 256, 2), 256>>>(s1, EE);

    // launch 11: classifier — A built on the fly = ACC3/Z3 + ACC4/Z4, bias folded
    GemmP gc = {};
    gc.z[0] = {ACC3, ACC4, Zs[3], Zs[4], linW, (float*)d_out, nullptr, nullptr, nullptr, nullptr};
    gc.z[1] = gc.z[0];
    gc.z[2] = gc.z[0];
    gc.bias = pLB2; gc.M = NN; gc.Nc = NOUT;
    gemm_v3_kernel<1, false><<<dim3((NN + 127) / 128, (NOUT + 127) / 128, 1), 256>>>(gc);
}

// round 6
// speedup vs baseline: 2.3112x; 1.0918x over previous
#include <cuda_runtime.h>
#include <cstdint>

// ---------------- problem constants ----------------
#define NN      100000
#define EE      250000
#define HH      4
#define HD      128
#define NOUT    349

// ---------------- device scratch ----------------
__device__ float g_H  [3ll * NN * HD];   // per-relation h = x@W
__device__ float g_ACC[5ll * NN * HD];   // unnormalized message sums
__device__ float g_X  [2ll * NN * HD];   // XP1, XA1
__device__ float g_P  [6ll * NN * HH];   // attention logit buffers [n*4+h]
__device__ float g_Z  [5ll * NN * HH];   // softmax denominators
__device__ float g_V  [3 * HD * HH];     // W·att_d vectors
__device__ float g_LB2[NOUT];            // folded classifier bias

// ---------------- prep ----------------
struct PrepParams {
    const float* W[3];
    const float* att[3];
    float* V;
    const float* linW;
    const float* linb;
    const float* bc;
    const float* bw;
    float* linb2;
};

__global__ void prep_all_kernel(PrepParams p)
{
    int b = blockIdx.x;
    if (b < 3) {
        int k = threadIdx.x;
        if (k >= HD) return;
        const float* W   = p.W[b];
        const float* att = p.att[b];
        #pragma unroll
        for (int h = 0; h < HH; h++) {
            float s = 0.f;
            #pragma unroll
            for (int c = 0; c < 32; c++)
                s += W[k * HD + h * 32 + c] * att[h * 32 + c];
            p.V[b * (HD * HH) + k * HH + h] = s;
        }
    } else {
        int o = (b - 3) * 256 + threadIdx.x;
        if (o >= NOUT) return;
        float s = p.linb[o];
        #pragma unroll 4
        for (int j = 0; j < HD; j++)
            s += (p.bc[j] + p.bw[j]) * p.linW[(size_t)j * NOUT + o];
        p.linb2[o] = s;
    }
}

// ---------------- dst-side projections ----------------
struct ProjP {
    const float* x[2];
    const float* V[2];
    float*       out[2];
};

__global__ void __launch_bounds__(256) proj_dst_kernel(ProjP p, int n)
{
    int s = blockIdx.y;
    const float* x = p.x[s];
    const float* V = p.V[s];
    float* out = p.out[s];

    int lane   = threadIdx.x & 31;
    int warp   = (blockIdx.x * blockDim.x + threadIdx.x) >> 5;
    int nwarps = (gridDim.x * blockDim.x) >> 5;

    const float4* V4 = reinterpret_cast<const float4*>(V);
    float4 v0 = V4[lane * 4 + 0];
    float4 v1 = V4[lane * 4 + 1];
    float4 v2 = V4[lane * 4 + 2];
    float4 v3 = V4[lane * 4 + 3];

    const float4* x4 = reinterpret_cast<const float4*>(x);
    for (int node = warp; node < n; node += nwarps) {
        float4 xv = x4[(size_t)node * 32 + lane];
        float4 a;
        a.x = xv.x * v0.x + xv.y * v1.x + xv.z * v2.x + xv.w * v3.x;
        a.y = xv.x * v0.y + xv.y * v1.y + xv.z * v2.y + xv.w * v3.y;
        a.z = xv.x * v0.z + xv.y * v1.z + xv.z * v2.z + xv.w * v3.z;
        a.w = xv.x * v0.w + xv.y * v1.w + xv.z * v2.w + xv.w * v3.w;
        #pragma unroll
        for (int off = 16; off; off >>= 1) {
            a.x += __shfl_xor_sync(0xffffffff, a.x, off);
            a.y += __shfl_xor_sync(0xffffffff, a.y, off);
            a.z += __shfl_xor_sync(0xffffffff, a.z, off);
            a.w += __shfl_xor_sync(0xffffffff, a.w, off);
        }
        if (lane == 0)
            reinterpret_cast<float4*>(out)[node] = a;
    }
}

// ---------------- fused edge kernel: exp + Z + message scatter -------------
struct ScP {
    const int*   ei[3];
    const float* h[3];
    const float* AS[3];
    const float* AD[3];
    float*       acc[3];
    float*       Z[3];
};

__global__ void scatter_kernel(ScP p, int E)
{
    int rel  = blockIdx.y;
    int e    = (blockIdx.x * blockDim.x + threadIdx.x) >> 5;
    int lane = threadIdx.x & 31;
    if (e >= E) return;
    const int* ei = p.ei[rel];
    int src = ei[e];
    int dst = ei[E + e];
    int hh  = lane >> 3;

    float as = p.AS[rel][src * HH + hh];
    float ad = p.AD[rel][dst * HH + hh];
    float t  = as + ad;
    t = fmaxf(t, 0.2f * t);
    float w = __expf(t);

    float4 hv = *reinterpret_cast<const float4*>(p.h[rel] + (size_t)src * HD + lane * 4);
    float4 m  = make_float4(hv.x * w, hv.y * w, hv.z * w, hv.w * w);
    atomicAdd(reinterpret_cast<float4*>(p.acc[rel] + (size_t)dst * HD + lane * 4), m);
    if ((lane & 7) == 0)
        atomicAdd(p.Z[rel] + (size_t)dst * HH + hh, w);
}

// ---------------- combine: normalize + bias + act (+ dst proj) -------------
template <int NACC, int NV>
__global__ void __launch_bounds__(256) combine_kernel(
    const float* __restrict__ A0, const float* __restrict__ Z0,
    const float* __restrict__ A1, const float* __restrict__ Z1,
    const float* __restrict__ b1, const float* __restrict__ b2,
    const float* __restrict__ V,
    float* __restrict__ X, float* __restrict__ P, int n)
{
    int lane   = threadIdx.x & 31;
    int warp   = (blockIdx.x * blockDim.x + threadIdx.x) >> 5;
    int nwarps = (gridDim.x * blockDim.x) >> 5;
    int hh     = lane >> 3;

    float4 bb = reinterpret_cast<const float4*>(b1)[lane];
    if (NACC == 2) {
        float4 t = reinterpret_cast<const float4*>(b2)[lane];
        bb.x += t.x; bb.y += t.y; bb.z += t.z; bb.w += t.w;
    }

    float4 v0, v1, v2, v3;
    if (NV) {
        const float4* V4 = reinterpret_cast<const float4*>(V);
        v0 = V4[lane * 4 + 0];
        v1 = V4[lane * 4 + 1];
        v2 = V4[lane * 4 + 2];
        v3 = V4[lane * 4 + 3];
    }

    for (int node = warp; node < n; node += nwarps) {
        float i0 = 1.f / (Z0[(size_t)node * HH + hh] + 1e-16f);
        float4 xv = *reinterpret_cast<const float4*>(A0 + (size_t)node * HD + lane * 4);
        xv.x *= i0; xv.y *= i0; xv.z *= i0; xv.w *= i0;
        if (NACC == 2) {
            float i1 = 1.f / (Z1[(size_t)node * HH + hh] + 1e-16f);
            float4 t = *reinterpret_cast<const float4*>(A1 + (size_t)node * HD + lane * 4);
            xv.x += t.x * i1; xv.y += t.y * i1; xv.z += t.z * i1; xv.w += t.w * i1;
        }
        xv.x += bb.x; xv.y += bb.y; xv.z += bb.z; xv.w += bb.w;
        xv.x = fmaxf(xv.x, 0.01f * xv.x);
        xv.y = fmaxf(xv.y, 0.01f * xv.y);
        xv.z = fmaxf(xv.z, 0.01f * xv.z);
        xv.w = fmaxf(xv.w, 0.01f * xv.w);
        reinterpret_cast<float4*>(X)[(size_t)node * 32 + lane] = xv;

        if (NV) {
            float4 a;
            a.x = xv.x * v0.x + xv.y * v1.x + xv.z * v2.x + xv.w * v3.x;
            a.y = xv.x * v0.y + xv.y * v1.y + xv.z * v2.y + xv.w * v3.y;
            a.z = xv.x * v0.z + xv.y * v1.z + xv.z * v2.z + xv.w * v3.z;
            a.w = xv.x * v0.w + xv.y * v1.w + xv.z * v2.w + xv.w * v3.w;
            #pragma unroll
            for (int off = 16; off; off >>= 1) {
                a.x += __shfl_xor_sync(0xffffffff, a.x, off);
                a.y += __shfl_xor_sync(0xffffffff, a.y, off);
                a.z += __shfl_xor_sync(0xffffffff, a.z, off);
                a.w += __shfl_xor_sync(0xffffffff, a.w, off);
            }
            if (lane == 0)
                reinterpret_cast<float4*>(P)[node] = a;
        }
    }
}

// ---------------- tf32 tensor-core GEMM v4 (cp.async pipelined) ------------
// C[M,Nc] = A[M,128] @ B[128,Nc] (+bias), K=128, chunks of 32.
// Block 128x128, 8 warps (2M x 4N), warp tile 64x32, mma.m16n8k8.tf32.
// Raw chunks fetched via cp.async.cg into double buffers (latency hidden);
// convert phase builds fragment-major smem; compute unchanged from v3.
// AMODE=1: A rows = A/Za + A1/Zb (per-head normalize), B staged via LDG.

__device__ __forceinline__ uint32_t f2tf32(float x) {
    uint32_t r; asm("cvt.rna.tf32.f32 %0, %1;" : "=r"(r) : "f"(x)); return r;
}

__device__ __forceinline__ void mma_tf32(float& c0, float& c1, float& c2, float& c3,
                                         uint32_t a0, uint32_t a1, uint32_t a2, uint32_t a3,
                                         uint32_t b0, uint32_t b1)
{
    asm volatile(
        "mma.sync.aligned.m16n8k8.row.col.f32.tf32.tf32.f32 "
        "{%0,%1,%2,%3}, {%4,%5,%6,%7}, {%8,%9}, {%0,%1,%2,%3};"
        : "+f"(c0), "+f"(c1), "+f"(c2), "+f"(c3)
        : "r"(a0), "r"(a1), "r"(a2), "r"(a3), "r"(b0), "r"(b1));
}

__device__ __forceinline__ void cp_async16(uint32_t dst, const void* src, int sz) {
    asm volatile("cp.async.cg.shared.global [%0], [%1], 16, %2;"
                 :: "r"(dst), "l"(src), "r"(sz));
}

struct GemmZ {
    const float* A;
    const float* A1;
    const float* Za;
    const float* Zb;
    const float* B;
    float*       C;
    const float* attS;
    const float* attD;
    float*       PS;
    float*       PD;
};
struct GemmP {
    GemmZ z[3];
    const float* bias;
    int M, Nc;
};

#define GEMM_SMEM_BYTES 98304   // Af 16K + Bf 16K + rawA 32K + rawB/rawA1 32K

template <int AMODE, bool ALIGNED>
__global__ void __launch_bounds__(256, 2) gemm_v4_kernel(GemmP p)
{
    extern __shared__ uint8_t smem_raw[];
    uint32_t* Af   = reinterpret_cast<uint32_t*>(smem_raw);           // 4096 words
    uint32_t* Bf   = Af + 4096;                                       // 4096 words
    float4*   rawA = reinterpret_cast<float4*>(Bf + 4096);            // 2 x 1024 f4
    float4*   rawB = rawA + 2048;                                     // 2 x 1024 f4

    const uint32_t sA = (uint32_t)__cvta_generic_to_shared(rawA);
    const uint32_t sB = (uint32_t)__cvta_generic_to_shared(rawB);

    const GemmZ zp = p.z[blockIdx.z];
    const int M = p.M, Nc = p.Nc;

    const int tid  = threadIdx.x;
    const int lane = tid & 31;
    const int w    = tid >> 5;
    const int wm   = w & 1;
    const int wn   = w >> 1;
    const int m0   = blockIdx.x * 128;
    const int n0   = blockIdx.y * 128;

    const int gA   = lane >> 3;      // 0..3
    const int kcA  = lane & 7;       // 0..7
    const int rotA = (gA + (kcA >> 1)) & 3;
    const int lidx = gA * 8 + kcA;   // == lane

    // ---- async stage of chunk c into buffer buf ----
    auto stageAsync = [&](int c, int buf) {
        #pragma unroll
        for (int it = 0; it < 4; it++) {
            int qg = it * 8 + w;
            int r  = qg * 4 + gA;
            int gm = m0 + r;
            uint32_t dst = sA + (buf * 1024 + qg * 32 + lidx) * 16;
            const float* src = zp.A + (size_t)gm * 128 + c * 32 + kcA * 4;
            cp_async16(dst, src, (gm < M) ? 16 : 0);
        }
        if (AMODE == 1) {
            #pragma unroll
            for (int it = 0; it < 4; it++) {
                int qg = it * 8 + w;
                int r  = qg * 4 + gA;
                int gm = m0 + r;
                uint32_t dst = sB + (buf * 1024 + qg * 32 + lidx) * 16;
                const float* src = zp.A1 + (size_t)gm * 128 + c * 32 + kcA * 4;
                cp_async16(dst, src, (gm < M) ? 16 : 0);
            }
        } else if (ALIGNED) {
            #pragma unroll
            for (int it = 0; it < 4; it++) {
                int qg  = it * 8 + w;
                int krl = (qg & 7) * 4 + gA;
                int kr  = c * 32 + krl;
                int nf  = (qg >> 3) * 8 + kcA;
                uint32_t dst = sB + (buf * 1024 + qg * 32 + lidx) * 16;
                const float* src = zp.B + (size_t)kr * Nc + n0 + nf * 4;
                cp_async16(dst, src, 16);
            }
        }
        asm volatile("cp.async.commit_group;" ::: "memory");
    };

    // ---- convert raw chunk -> fragment layout ----
    auto convert = [&](int c, int buf) {
        // A fragments
        {
            int k8c = kcA >> 1;
            int khi = kcA & 1;
            #pragma unroll
            for (int it = 0; it < 4; it++) {
                int qg = it * 8 + w;
                int r  = qg * 4 + gA;
                float4 v = rawA[buf * 1024 + qg * 32 + lidx];
                if (AMODE == 1) {
                    int gm = m0 + r;
                    if (gm < M) {
                        float ia = 1.f / (zp.Za[(size_t)gm * HH + c] + 1e-16f);
                        float ib = 1.f / (zp.Zb[(size_t)gm * HH + c] + 1e-16f);
                        float4 u1 = rawB[buf * 1024 + qg * 32 + lidx];
                        v.x = v.x * ia + u1.x * ib;
                        v.y = v.y * ia + u1.y * ib;
                        v.z = v.z * ia + u1.z * ib;
                        v.w = v.w * ia + u1.w * ib;
                    }
                }
                int reg = (khi << 1) | ((r >> 3) & 1);
                uint32_t* base = &Af[((k8c << 3) + (r >> 4)) * 128 + reg];
                float vals[4] = {v.x, v.y, v.z, v.w};
                #pragma unroll
                for (int s = 0; s < 4; s++) {
                    int j = (s + rotA) & 3;
                    base[(((r & 7) << 2) + j) << 2] = f2tf32(vals[j]);
                }
            }
        }
        // B fragments
        #pragma unroll
        for (int it = 0; it < 4; it++) {
            int qg  = it * 8 + w;
            int krl = (qg & 7) * 4 + gA;
            int nf  = (qg >> 3) * 8 + kcA;
            float4 v;
            if (AMODE == 0 && ALIGNED) {
                v = rawB[buf * 1024 + qg * 32 + lidx];
            } else {
                int kr = c * 32 + krl;
                int gn = n0 + nf * 4;
                v = make_float4(0.f, 0.f, 0.f, 0.f);
                if (gn + 0 < Nc) v.x = zp.B[(size_t)kr * Nc + gn + 0];
                if (gn + 1 < Nc) v.y = zp.B[(size_t)kr * Nc + gn + 1];
                if (gn + 2 < Nc) v.z = zp.B[(size_t)kr * Nc + gn + 2];
                if (gn + 3 < Nc) v.w = zp.B[(size_t)kr * Nc + gn + 3];
            }
            int k8c = krl >> 3;
            int reg = (krl >> 2) & 1;
            int kl  = krl & 3;
            float vals[4] = {v.x, v.y, v.z, v.w};
            #pragma unroll
            for (int s = 0; s < 4; s++) {
                int j = (s + kcA) & 3;
                int n = nf * 4 + j;
                Bf[((k8c << 4) + (n >> 3)) * 64 + ((((n & 7) << 2) + kl) << 1) + reg] = f2tf32(vals[j]);
            }
        }
    };

    float acc[4][4][4];
    #pragma unroll
    for (int i = 0; i < 4; i++)
        #pragma unroll
        for (int j = 0; j < 4; j++)
            #pragma unroll
            for (int q = 0; q < 4; q++) acc[i][j][q] = 0.f;

    stageAsync(0, 0);
    stageAsync(1, 1);

    #pragma unroll
    for (int c = 0; c < 4; c++) {
        if (c < 3) { asm volatile("cp.async.wait_group 1;" ::: "memory"); }
        else       { asm volatile("cp.async.wait_group 0;" ::: "memory"); }
        __syncthreads();              // raw chunk c visible to all
        convert(c, c & 1);
        __syncthreads();              // frag ready; raw[c&1] free
        if (c + 2 < 4) stageAsync(c + 2, c & 1);

        #pragma unroll
        for (int k8c = 0; k8c < 4; k8c++) {
            uint32_t a[4][4];
            uint32_t b[4][2];
            #pragma unroll
            for (int i = 0; i < 4; i++) {
                uint4 t = *reinterpret_cast<uint4*>(&Af[((k8c << 3) + wm * 4 + i) * 128 + (lane << 2)]);
                a[i][0] = t.x; a[i][1] = t.y; a[i][2] = t.z; a[i][3] = t.w;
            }
            #pragma unroll
            for (int j = 0; j < 4; j++) {
                uint2 t = *reinterpret_cast<uint2*>(&Bf[((k8c << 4) + wn * 4 + j) * 64 + (lane << 1)]);
                b[j][0] = t.x; b[j][1] = t.y;
            }
            #pragma unroll
            for (int i = 0; i < 4; i++)
                #pragma unroll
                for (int j = 0; j < 4; j++)
                    mma_tf32(acc[i][j][0], acc[i][j][1], acc[i][j][2], acc[i][j][3],
                             a[i][0], a[i][1], a[i][2], a[i][3], b[j][0], b[j][1]);
        }
        if (c < 3) __syncthreads();   // frag reads done before next convert
    }

    // ---- epilogue: C write ----
    const int gID = lane >> 2;
    const int tig = lane & 3;
    const float* bias = p.bias;
    #pragma unroll
    for (int i = 0; i < 4; i++) {
        int row0 = m0 + wm * 64 + i * 16 + gID;
        #pragma unroll
        for (int j = 0; j < 4; j++) {
            int col = n0 + wn * 32 + j * 8 + tig * 2;
            float bx = 0.f, by = 0.f;
            if (bias) {
                if (col < Nc)     bx = bias[col];
                if (col + 1 < Nc) by = bias[col + 1];
            }
            if (ALIGNED) {
                if (row0 < M) {
                    float2 o = make_float2(acc[i][j][0] + bx, acc[i][j][1] + by);
                    *reinterpret_cast<float2*>(zp.C + (size_t)row0 * Nc + col) = o;
                }
                if (row0 + 8 < M) {
                    float2 o = make_float2(acc[i][j][2] + bx, acc[i][j][3] + by);
                    *reinterpret_cast<float2*>(zp.C + (size_t)(row0 + 8) * Nc + col) = o;
                }
            } else {
                if (row0 < M) {
                    if (col < Nc)     zp.C[(size_t)row0 * Nc + col]     = acc[i][j][0] + bx;
                    if (col + 1 < Nc) zp.C[(size_t)row0 * Nc + col + 1] = acc[i][j][1] + by;
                }
                if (row0 + 8 < M) {
                    if (col < Nc)     zp.C[(size_t)(row0 + 8) * Nc + col]     = acc[i][j][2] + bx;
                    if (col + 1 < Nc) zp.C[(size_t)(row0 + 8) * Nc + col + 1] = acc[i][j][3] + by;
                }
            }
        }
    }

    // ---- epilogue: attention dots (head == warp column wn) ----
    if (AMODE == 0 && zp.attS) {
        bool hasD = (zp.attD != nullptr);
        float aS[4][2], aD[4][2];
        #pragma unroll
        for (int j = 0; j < 4; j++) {
            int cc = wn * 32 + j * 8 + tig * 2;
            aS[j][0] = zp.attS[cc];
            aS[j][1] = zp.attS[cc + 1];
            if (hasD) { aD[j][0] = zp.attD[cc]; aD[j][1] = zp.attD[cc + 1]; }
        }
        #pragma unroll
        for (int i = 0; i < 4; i++) {
            float s0 = 0.f, s1 = 0.f, d0 = 0.f, d1 = 0.f;
            #pragma unroll
            for (int j = 0; j < 4; j++) {
                s0 += acc[i][j][0] * aS[j][0] + acc[i][j][1] * aS[j][1];
                s1 += acc[i][j][2] * aS[j][0] + acc[i][j][3] * aS[j][1];
                if (hasD) {
                    d0 += acc[i][j][0] * aD[j][0] + acc[i][j][1] * aD[j][1];
                    d1 += acc[i][j][2] * aD[j][0] + acc[i][j][3] * aD[j][1];
                }
            }
            s0 += __shfl_xor_sync(0xffffffff, s0, 1); s0 += __shfl_xor_sync(0xffffffff, s0, 2);
            s1 += __shfl_xor_sync(0xffffffff, s1, 1); s1 += __shfl_xor_sync(0xffffffff, s1, 2);
            if (hasD) {
                d0 += __shfl_xor_sync(0xffffffff, d0, 1); d0 += __shfl_xor_sync(0xffffffff, d0, 2);
                d1 += __shfl_xor_sync(0xffffffff, d1, 1); d1 += __shfl_xor_sync(0xffffffff, d1, 2);
            }
            if (tig == 0) {
                int r0 = m0 + wm * 64 + i * 16 + gID;
                if (r0 < M)     zp.PS[(size_t)r0 * HH + wn]       = s0;
                if (r0 + 8 < M) zp.PS[(size_t)(r0 + 8) * HH + wn] = s1;
                if (hasD) {
                    if (r0 < M)     zp.PD[(size_t)r0 * HH + wn]       = d0;
                    if (r0 + 8 < M) zp.PD[(size_t)(r0 + 8) * HH + wn] = d1;
                }
            }
        }
    }
}

// ---------------- host launch ----------------
extern "C" void kernel_launch(void* const* d_in, const int* in_sizes, int n_in,
                              void* d_out, int out_size)
{
    const float* xs[2]   = {nullptr, nullptr}; int nx = 0;
    const int*   eis[3]  = {nullptr, nullptr, nullptr}; int ne = 0;
    const float* Ws[6]   = {}; int nw = 0;
    const float* attb[18]= {}; int na = 0;
    const float* linW = nullptr;
    const float* linb = nullptr;

    for (int i = 0; i < n_in; i++) {
        int s = in_sizes[i];
        if      (s == NN * HD    && nx < 2)  xs[nx++]   = (const float*)d_in[i];
        else if (s == 2 * EE     && ne < 3)  eis[ne++]  = (const int*)d_in[i];
        else if (s == HD * HD    && nw < 6)  Ws[nw++]   = (const float*)d_in[i];
        else if (s == HD         && na < 18) attb[na++] = (const float*)d_in[i];
        else if (s == HD * NOUT)             linW       = (const float*)d_in[i];
        else if (s == NOUT)                  linb       = (const float*)d_in[i];
    }
    if (nx != 2 || ne != 3 || nw != 6 || na != 18 || !linW || !linb) return;

    static bool attr_done = false;
    if (!attr_done) {
        cudaFuncSetAttribute(gemm_v4_kernel<0, true>,
                             cudaFuncAttributeMaxDynamicSharedMemorySize, GEMM_SMEM_BYTES);
        cudaFuncSetAttribute(gemm_v4_kernel<1, false>,
                             cudaFuncAttributeMaxDynamicSharedMemorySize, GEMM_SMEM_BYTES);
        attr_done = true;
    }

    float *pH, *pACC, *pX, *pP, *pZ, *pV, *pLB2;
    cudaGetSymbolAddress((void**)&pH,   g_H);
    cudaGetSymbolAddress((void**)&pACC, g_ACC);
    cudaGetSymbolAddress((void**)&pX,   g_X);
    cudaGetSymbolAddress((void**)&pP,   g_P);
    cudaGetSymbolAddress((void**)&pZ,   g_Z);
    cudaGetSymbolAddress((void**)&pV,   g_V);
    cudaGetSymbolAddress((void**)&pLB2, g_LB2);

    const size_t FEAT = (size_t)NN * HD;
    float* H0  = pH;
    float* H1  = pH + FEAT;
    float* H2  = pH + 2 * FEAT;
    float* ACC0 = pACC;
    float* ACC1 = pACC + FEAT;
    float* ACC2 = pACC + 2 * FEAT;
    float* ACC3 = pACC + 3 * FEAT;
    float* ACC4 = pACC + 4 * FEAT;
    float* XP1 = pX;
    float* XA1 = pX + FEAT;
    float* Pb[6];
    for (int i = 0; i < 6; i++) Pb[i] = pP + (size_t)i * NN * HH;
    float* Zs[5];
    for (int i = 0; i < 5; i++) Zs[i] = pZ + (size_t)i * NN * HH;
    float* v0 = pV;
    float* v1 = pV + 512;
    float* v2 = pV + 1024;

    // launches 0..2: memsets
    cudaMemsetAsync(pACC, 0, 3 * FEAT * sizeof(float));
    cudaMemsetAsync(pACC + 3 * FEAT, 0, 2 * FEAT * sizeof(float));
    cudaMemsetAsync(pZ,   0, 5 * (size_t)NN * HH * sizeof(float));

    // launch 3: prep
    PrepParams pp;
    pp.W[0] = Ws[1]; pp.att[0] = attb[4];    // ad0_w
    pp.W[1] = Ws[2]; pp.att[1] = attb[7];    // ad0_wb
    pp.W[2] = Ws[4]; pp.att[2] = attb[13];   // ad1_w
    pp.V = pV; pp.linW = linW; pp.linb = linb;
    pp.bc = attb[11]; pp.bw = attb[14]; pp.linb2 = pLB2;
    prep_all_kernel<<<5, 256>>>(pp);

    // launch 4: dst-side projections for L0
    ProjP prj;
    prj.x[0] = xs[0]; prj.V[0] = v0; prj.out[0] = Pb[3];
    prj.x[1] = xs[1]; prj.V[1] = v1; prj.out[1] = Pb[5];
    proj_dst_kernel<<<dim3(512, 2), 256>>>(prj, NN);

    // launch 5 (ncu target): L0 GEMMs + epilogue attention dots
    GemmP g0 = {};
    g0.z[0] = {xs[0], nullptr, nullptr, nullptr, Ws[0], H0, attb[0], attb[1], Pb[0], Pb[1]};
    g0.z[1] = {xs[1], nullptr, nullptr, nullptr, Ws[1], H1, attb[3], nullptr, Pb[2], nullptr};
    g0.z[2] = {xs[0], nullptr, nullptr, nullptr, Ws[2], H2, attb[6], nullptr, Pb[4], nullptr};
    g0.bias = nullptr; g0.M = NN; g0.Nc = HD;
    gemm_v4_kernel<0, true><<<dim3((NN + 127) / 128, 1, 3), 256, GEMM_SMEM_BYTES>>>(g0);

    // launch 6: L0 scatter
    ScP s0;
    s0.ei[0] = eis[0]; s0.h[0] = H0; s0.AS[0] = Pb[0]; s0.AD[0] = Pb[1]; s0.acc[0] = ACC0; s0.Z[0] = Zs[0];
    s0.ei[1] = eis[1]; s0.h[1] = H1; s0.AS[1] = Pb[2]; s0.AD[1] = Pb[3]; s0.acc[1] = ACC1; s0.Z[1] = Zs[1];
    s0.ei[2] = eis[2]; s0.h[2] = H2; s0.AS[2] = Pb[4]; s0.AD[2] = Pb[5]; s0.acc[2] = ACC2; s0.Z[2] = Zs[2];
    scatter_kernel<<<dim3((EE * 32 + 255) / 256, 3), 256>>>(s0, EE);

    // launches 7,8: combine
    combine_kernel<2, 1><<<1024, 256>>>(ACC0, Zs[0], ACC1, Zs[1],
                                        attb[2], attb[5], v2, XP1, Pb[3], NN);
    combine_kernel<1, 0><<<1024, 256>>>(ACC2, Zs[2], nullptr, nullptr,
                                        attb[8], nullptr, nullptr, XA1, nullptr, NN);

    // launch 9: L1 GEMMs + epilogue dots
    GemmP g1 = {};
    g1.z[0] = {XP1, nullptr, nullptr, nullptr, Ws[3], H0, attb[9],  attb[10], Pb[0], Pb[1]};
    g1.z[1] = {XA1, nullptr, nullptr, nullptr, Ws[4], H1, attb[12], nullptr,  Pb[2], nullptr};
    g1.z[2] = g1.z[0];
    g1.bias = nullptr; g1.M = NN; g1.Nc = HD;
    gemm_v4_kernel<0, true><<<dim3((NN + 127) / 128, 1, 2), 256, GEMM_SMEM_BYTES>>>(g1);

    // launch 10: L1 scatter
    ScP s1;
    s1.ei[0] = eis[0]; s1.h[0] = H0; s1.AS[0] = Pb[0]; s1.AD[0] = Pb[1]; s1.acc[0] = ACC3; s1.Z[0] = Zs[3];
    s1.ei[1] = eis[1]; s1.h[1] = H1; s1.AS[1] = Pb[2]; s1.AD[1] = Pb[3]; s1.acc[1] = ACC4; s1.Z[1] = Zs[4];
    s1.ei[2] = s1.ei[0]; s1.h[2] = s1.h[0]; s1.AS[2] = s1.AS[0]; s1.AD[2] = s1.AD[0];
    s1.acc[2] = ACC3; s1.Z[2] = Zs[3];
    scatter_kernel<<<dim3((EE * 32 + 255) / 256, 2), 256>>>(s1, EE);

    // launch 11: classifier (A built on the fly, bias folded)
    GemmP gc = {};
    gc.z[0] = {ACC3, ACC4, Zs[3], Zs[4], linW, (float*)d_out, nullptr, nullptr, nullptr, nullptr};
    gc.z[1] = gc.z[0];
    gc.z[2] = gc.z[0];
    gc.bias = pLB2; gc.M = NN; gc.Nc = NOUT;
    gemm_v4_kernel<1, false><<<dim3((NN + 127) / 128, (NOUT + 127) / 128, 1), 256, GEMM_SMEM_BYTES>>>(gc);
}